// round 1
// baseline (speedup 1.0000x reference)
#include <cuda_runtime.h>
#include <cuda_bf16.h>

#define N_NODES 70000
#define N_EDGES 800000
#define IN_SAGE 1024
#define FEAT_CH 128
#define EXTRA 20
#define HIDDEN 37        // (128+20)/4
#define OUT_CH 3
#define FDIM 1044
#define FC1_IN 148       // FEAT_CH + EXTRA

// ---------------- scratch (device globals; no allocation allowed) ----------
__device__ float g_yl[(size_t)N_NODES * FEAT_CH];   // x_in @ Wl^T
__device__ float g_yr[(size_t)N_NODES * FEAT_CH];   // x_in @ Wr^T
__device__ float g_agg[(size_t)N_NODES * FEAT_CH];  // segment_sum(y_l[src], dst)
__device__ float g_cnt[N_NODES];

// ---------------- kernel 1: zero scratch -----------------------------------
__global__ void zero_kernel() {
    size_t i = (size_t)blockIdx.x * blockDim.x + threadIdx.x;
    const size_t NA = (size_t)N_NODES * FEAT_CH;
    if (i < NA) g_agg[i] = 0.0f;
    if (i < N_NODES) g_cnt[i] = 0.0f;
}

// ---------------- kernel 2: fp32 tiled GEMM --------------------------------
// Computes Y = X[:, :1024] @ W^T for W in {Wl, Wr} (blockIdx.y selects).
// X: [N_NODES, 1044] row-major (use first 1024 cols). W: [128, 1024] row-major.
// Tile: BM=128, BN=128(full weight rows), BK=16. 256 threads, 8x8 per thread.
#define BM 128
#define BN 128
#define BK 16
__global__ __launch_bounds__(256) void gemm_kernel(
    const float* __restrict__ X,
    const float* __restrict__ Wl,
    const float* __restrict__ Wr)
{
    __shared__ float As[BK][BM];
    __shared__ float Bs[BK][BN];

    const float* W = (blockIdx.y == 0) ? Wl : Wr;
    float* Y       = (blockIdx.y == 0) ? g_yl : g_yr;

    const int m0  = blockIdx.x * BM;
    const int tid = threadIdx.x;
    const int ty  = tid >> 4;   // 0..15
    const int tx  = tid & 15;   // 0..15

    float acc[8][8];
#pragma unroll
    for (int i = 0; i < 8; i++)
#pragma unroll
        for (int j = 0; j < 8; j++) acc[i][j] = 0.0f;

    for (int k0 = 0; k0 < IN_SAGE; k0 += BK) {
        // A tile: 128 rows x 16 cols = 512 float4, 2 per thread
#pragma unroll
        for (int t = 0; t < 2; t++) {
            int f   = tid + t * 256;
            int row = f >> 2;
            int kq  = (f & 3) << 2;
            float4 v = make_float4(0.f, 0.f, 0.f, 0.f);
            int m = m0 + row;
            if (m < N_NODES)
                v = *(const float4*)(X + (size_t)m * FDIM + k0 + kq);
            As[kq + 0][row] = v.x;
            As[kq + 1][row] = v.y;
            As[kq + 2][row] = v.z;
            As[kq + 3][row] = v.w;
        }
        // B tile: 128 rows (n) x 16 cols (k)
#pragma unroll
        for (int t = 0; t < 2; t++) {
            int f  = tid + t * 256;
            int n  = f >> 2;
            int kq = (f & 3) << 2;
            float4 v = *(const float4*)(W + (size_t)n * IN_SAGE + k0 + kq);
            Bs[kq + 0][n] = v.x;
            Bs[kq + 1][n] = v.y;
            Bs[kq + 2][n] = v.z;
            Bs[kq + 3][n] = v.w;
        }
        __syncthreads();

#pragma unroll
        for (int k = 0; k < BK; k++) {
            float a[8], b[8];
#pragma unroll
            for (int i = 0; i < 8; i++) a[i] = As[k][ty * 8 + i];
#pragma unroll
            for (int i = 0; i < 8; i++) b[i] = Bs[k][tx * 8 + i];
#pragma unroll
            for (int i = 0; i < 8; i++)
#pragma unroll
                for (int j = 0; j < 8; j++)
                    acc[i][j] = fmaf(a[i], b[j], acc[i][j]);
        }
        __syncthreads();
    }

#pragma unroll
    for (int i = 0; i < 8; i++) {
        int m = m0 + ty * 8 + i;
        if (m < N_NODES) {
            float* yp = Y + (size_t)m * FEAT_CH + tx * 8;
#pragma unroll
            for (int j = 0; j < 8; j += 4)
                *(float4*)(yp + j) =
                    make_float4(acc[i][j], acc[i][j + 1], acc[i][j + 2], acc[i][j + 3]);
        }
    }
}

// ---------------- kernel 3: edge scatter (warp per edge) -------------------
__global__ __launch_bounds__(256) void edge_kernel(const int* __restrict__ edges) {
    int warp = (blockIdx.x * blockDim.x + threadIdx.x) >> 5;
    int lane = threadIdx.x & 31;
    if (warp >= N_EDGES) return;
    int src = edges[warp];             // edges[0][e]
    int dst = edges[N_EDGES + warp];   // edges[1][e]
    const float4 v = *(const float4*)(g_yl + (size_t)src * FEAT_CH + lane * 4);
    float* a = g_agg + (size_t)dst * FEAT_CH + lane * 4;
    atomicAdd(a + 0, v.x);
    atomicAdd(a + 1, v.y);
    atomicAdd(a + 2, v.z);
    atomicAdd(a + 3, v.w);
    if (lane == 0) atomicAdd(&g_cnt[dst], 1.0f);
}

// ---------------- kernel 4: fused mean+relu+concat+fc1+bn+fc2 --------------
__global__ __launch_bounds__(256) void final_kernel(
    const float* __restrict__ feats,
    const float* __restrict__ b_sage,
    const float* __restrict__ fc1_w, const float* __restrict__ fc1_b,
    const float* __restrict__ fc2_w, const float* __restrict__ fc2_b,
    const float* __restrict__ bn_g,  const float* __restrict__ bn_b,
    const float* __restrict__ bn_m,  const float* __restrict__ bn_v,
    float* __restrict__ out)
{
    __shared__ float w1[HIDDEN * FC1_IN];
    __shared__ float b1[HIDDEN], bs[FEAT_CH];
    __shared__ float sc[HIDDEN], tr[HIDDEN];
    __shared__ float w2[OUT_CH * HIDDEN], b2[OUT_CH];

    for (int i = threadIdx.x; i < HIDDEN * FC1_IN; i += blockDim.x) w1[i] = fc1_w[i];
    for (int i = threadIdx.x; i < FEAT_CH; i += blockDim.x) bs[i] = b_sage[i];
    for (int i = threadIdx.x; i < OUT_CH * HIDDEN; i += blockDim.x) w2[i] = fc2_w[i];
    if (threadIdx.x < HIDDEN) {
        int j = threadIdx.x;
        b1[j] = fc1_b[j];
        float s = bn_g[j] * rsqrtf(bn_v[j] + 1e-5f);
        sc[j] = s;
        tr[j] = bn_b[j] - bn_m[j] * s;
    }
    if (threadIdx.x < OUT_CH) b2[threadIdx.x] = fc2_b[threadIdx.x];
    __syncthreads();

    int node = blockIdx.x * blockDim.x + threadIdx.x;
    if (node >= N_NODES) return;

    float z[HIDDEN];
#pragma unroll
    for (int j = 0; j < HIDDEN; j++) z[j] = b1[j];

    float inv = 1.0f / fmaxf(g_cnt[node], 1.0f);
    const float* aggp = g_agg + (size_t)node * FEAT_CH;
    const float* yrp  = g_yr  + (size_t)node * FEAT_CH;

    for (int i = 0; i < FEAT_CH; i++) {
        float v = fmaxf(aggp[i] * inv + bs[i] + yrp[i], 0.0f);
#pragma unroll
        for (int j = 0; j < HIDDEN; j++)
            z[j] = fmaf(w1[j * FC1_IN + i], v, z[j]);
    }
    const float* ex = feats + (size_t)node * FDIM + IN_SAGE;
    for (int i = 0; i < EXTRA; i++) {
        float v = ex[i];  // extras are NOT relu'd
#pragma unroll
        for (int j = 0; j < HIDDEN; j++)
            z[j] = fmaf(w1[j * FC1_IN + FEAT_CH + i], v, z[j]);
    }
#pragma unroll
    for (int j = 0; j < HIDDEN; j++)
        z[j] = fmaxf(z[j], 0.0f) * sc[j] + tr[j];

#pragma unroll
    for (int k = 0; k < OUT_CH; k++) {
        float s = b2[k];
#pragma unroll
        for (int j = 0; j < HIDDEN; j++)
            s = fmaf(w2[k * HIDDEN + j], z[j], s);
        out[(size_t)node * OUT_CH + k] = s;
    }
}

// ---------------- launch ----------------------------------------------------
extern "C" void kernel_launch(void* const* d_in, const int* in_sizes, int n_in,
                              void* d_out, int out_size) {
    const float* features = (const float*)d_in[0];
    const int*   edges    = (const int*)  d_in[1];
    // d_in[2] = edges2 (unused by reference), d_in[3] = edge_features (unused)
    const float* w_sage_l = (const float*)d_in[4];
    const float* b_sage_l = (const float*)d_in[5];
    const float* w_sage_r = (const float*)d_in[6];
    const float* fc1_w    = (const float*)d_in[7];
    const float* fc1_b    = (const float*)d_in[8];
    const float* fc2_w    = (const float*)d_in[9];
    const float* fc2_b    = (const float*)d_in[10];
    const float* bn_g     = (const float*)d_in[11];
    const float* bn_b     = (const float*)d_in[12];
    const float* bn_m     = (const float*)d_in[13];
    const float* bn_v     = (const float*)d_in[14];
    float* out = (float*)d_out;

    const size_t NA = (size_t)N_NODES * FEAT_CH;
    zero_kernel<<<(int)((NA + 255) / 256), 256>>>();

    gemm_kernel<<<dim3((N_NODES + BM - 1) / BM, 2), 256>>>(features, w_sage_l, w_sage_r);

    edge_kernel<<<(N_EDGES * 32) / 256, 256>>>(edges);

    final_kernel<<<(N_NODES + 255) / 256, 256>>>(
        features, b_sage_l, fc1_w, fc1_b, fc2_w, fc2_b,
        bn_g, bn_b, bn_m, bn_v, out);
}

// round 4
// speedup vs baseline: 1.8034x; 1.8034x over previous
#include <cuda_runtime.h>
#include <cuda_bf16.h>
#include <cstdint>

#define N_NODES 70000
#define N_EDGES 800000
#define IN_SAGE 1024
#define FEAT_CH 128
#define EXTRA 20
#define HIDDEN 37        // (128+20)/4
#define OUT_CH 3
#define FDIM 1044
#define FC1_IN 148       // FEAT_CH + EXTRA

// ---------------- scratch (device globals; no allocation allowed) ----------
__device__ float g_yl[(size_t)N_NODES * FEAT_CH];   // x_in @ Wl^T
__device__ float g_yr[(size_t)N_NODES * FEAT_CH];   // x_in @ Wr^T
__device__ float g_agg[(size_t)N_NODES * FEAT_CH];  // segment_sum(y_l[src], dst)
__device__ float g_cnt[N_NODES];
__device__ __align__(16) __nv_bfloat16 g_whi[2 * FEAT_CH * IN_SAGE];  // bf16 hi
__device__ __align__(16) __nv_bfloat16 g_wlo[2 * FEAT_CH * IN_SAGE];  // bf16 lo

// pack two floats -> bf16x2 (lo 16 bits = a, hi 16 bits = b)
__device__ __forceinline__ uint32_t pack_bf16x2(float a, float b) {
    uint32_t r;
    asm("cvt.rn.bf16x2.f32 %0, %1, %2;" : "=r"(r) : "f"(b), "f"(a));
    return r;
}

// mma.sync m16n8k16 row.col bf16 x bf16 -> f32 (base PTX, no 'a' feature)
__device__ __forceinline__ void mma_bf16(float* c, const uint32_t* a, const uint32_t* b) {
    asm volatile(
        "mma.sync.aligned.m16n8k16.row.col.f32.bf16.bf16.f32 "
        "{%0,%1,%2,%3}, {%4,%5,%6,%7}, {%8,%9}, {%0,%1,%2,%3};"
        : "+f"(c[0]), "+f"(c[1]), "+f"(c[2]), "+f"(c[3])
        : "r"(a[0]), "r"(a[1]), "r"(a[2]), "r"(a[3]), "r"(b[0]), "r"(b[1]));
}

// ---------------- kernel 1: zero scratch -----------------------------------
__global__ void zero_kernel() {
    size_t i = (size_t)blockIdx.x * blockDim.x + threadIdx.x;
    const size_t NA = (size_t)N_NODES * FEAT_CH;
    if (i < NA) g_agg[i] = 0.0f;
    if (i < N_NODES) g_cnt[i] = 0.0f;
}

// ---------------- kernel 1b: split weights to bf16 hi/lo --------------------
__global__ void prep_w_kernel(const float* __restrict__ wl, const float* __restrict__ wr) {
    int i = blockIdx.x * blockDim.x + threadIdx.x;
    const int HALF = FEAT_CH * IN_SAGE;  // 131072 (pow2)
    if (i >= 2 * HALF) return;
    float v = (i < HALF) ? wl[i] : wr[i & (HALF - 1)];
    __nv_bfloat16 h = __float2bfloat16_rn(v);
    g_whi[i] = h;
    g_wlo[i] = __float2bfloat16_rn(v - __bfloat162float(h));
}

// ---------------- kernel 2: HMMA bf16 split GEMM ---------------------------
// Y[m][n] = sum_k X[m][k] * W[n][k]. grid.y: 0 -> Wl/g_yl, 1 -> Wr/g_yr.
// BM=128, BN=128, BK=32, double-buffered smem. hi/lo split: 3 MMA terms
// (Ahi*Bhi + Ahi*Blo + Alo*Bhi), fp32 accumulators.
#define BK2 32
#define ROWB 80                 // smem row stride bytes (40 bf16)
#define AH_OFF 0
#define AL_OFF 10240
#define BH_OFF 20480
#define BL_OFF 30720
#define STAGE_B 40960
#define GEMM_SMEM (2 * STAGE_B)

__device__ __forceinline__ void gemm_load_stage(
    char* st, const float* __restrict__ X,
    const __nv_bfloat16* __restrict__ Whi, const __nv_bfloat16* __restrict__ Wlo,
    int m0, int k0, int tid)
{
    // A: 128 rows x 32 k fp32 -> bf16 hi/lo. 1024 float4 tasks / 256 thr.
#pragma unroll
    for (int it = 0; it < 4; it++) {
        int idx = it * 256 + tid;
        int row = idx >> 3;
        int c4 = idx & 7;
        int m = m0 + row;
        float4 v = make_float4(0.f, 0.f, 0.f, 0.f);
        if (m < N_NODES)
            v = *(const float4*)(X + (size_t)m * FDIM + k0 + c4 * 4);
        uint32_t h01 = pack_bf16x2(v.x, v.y);
        uint32_t h23 = pack_bf16x2(v.z, v.w);
        float f0 = __uint_as_float(h01 << 16);
        float f1 = __uint_as_float(h01 & 0xffff0000u);
        float f2 = __uint_as_float(h23 << 16);
        float f3 = __uint_as_float(h23 & 0xffff0000u);
        uint32_t l01 = pack_bf16x2(v.x - f0, v.y - f1);
        uint32_t l23 = pack_bf16x2(v.z - f2, v.w - f3);
        *(uint2*)(st + AH_OFF + row * ROWB + c4 * 8) = make_uint2(h01, h23);
        *(uint2*)(st + AL_OFF + row * ROWB + c4 * 8) = make_uint2(l01, l23);
    }
    // B: hi+lo, 128 rows x 32 k bf16 each = 64 B/row -> 4 uint4 per row.
    // 2 sel * 128 rows * 4 quads = 1024 uint4 tasks / 256 thr.
#pragma unroll
    for (int it = 0; it < 4; it++) {
        int idx = it * 256 + tid;
        int sel = idx >> 9;                // 0=hi 1=lo
        int row = (idx >> 2) & 127;        // 0..127
        int c8 = idx & 3;                  // 0..3 (x8 bf16 = 16B)
        const __nv_bfloat16* src =
            (sel ? Wlo : Whi) + (size_t)row * IN_SAGE + k0 + c8 * 8;
        uint4 v = *(const uint4*)src;
        *(uint4*)(st + (sel ? BL_OFF : BH_OFF) + row * ROWB + c8 * 16) = v;
    }
}

__global__ void __launch_bounds__(256) gemm_kernel(const float* __restrict__ X) {
    extern __shared__ __align__(16) char sm[];
    const int tid = threadIdx.x;
    const int wid = tid >> 5;
    const int lane = tid & 31;
    const int gid = lane >> 2;   // 0..7
    const int ctg = lane & 3;    // 0..3
    const int warp_m = wid >> 2; // 0..1  (M64 each)
    const int warp_n = wid & 3;  // 0..3  (N32 each)
    const int mat = blockIdx.y;
    const int m0 = blockIdx.x * 128;

    const __nv_bfloat16* Whi = g_whi + (size_t)mat * (FEAT_CH * IN_SAGE);
    const __nv_bfloat16* Wlo = g_wlo + (size_t)mat * (FEAT_CH * IN_SAGE);
    float* Y = mat ? g_yr : g_yl;

    float acc[4][4][4];
#pragma unroll
    for (int i = 0; i < 4; i++)
#pragma unroll
        for (int j = 0; j < 4; j++)
#pragma unroll
            for (int r = 0; r < 4; r++) acc[i][j][r] = 0.0f;

    gemm_load_stage(sm, X, Whi, Wlo, m0, 0, tid);

    const int NCH = IN_SAGE / BK2;   // 32
    for (int c = 0; c < NCH; c++) {
        __syncthreads();
        char* st = sm + (c & 1) * STAGE_B;
        if (c + 1 < NCH)
            gemm_load_stage(sm + ((c + 1) & 1) * STAGE_B, X, Whi, Wlo,
                            m0, (c + 1) * BK2, tid);

#pragma unroll
        for (int ks = 0; ks < 2; ks++) {
            const int kb = ks * 16;
            const int kcol = (kb + 2 * ctg) * 2;   // byte offset of lane's k pair

            uint32_t bh[4][2], bl[4][2];
#pragma unroll
            for (int nt = 0; nt < 4; nt++) {
                const char* pb = st + (warp_n * 32 + nt * 8 + gid) * ROWB + kcol;
                bh[nt][0] = *(const uint32_t*)(pb + BH_OFF);
                bh[nt][1] = *(const uint32_t*)(pb + BH_OFF + 16);
                bl[nt][0] = *(const uint32_t*)(pb + BL_OFF);
                bl[nt][1] = *(const uint32_t*)(pb + BL_OFF + 16);
            }
#pragma unroll
            for (int mt = 0; mt < 4; mt++) {
                const char* pa = st + (warp_m * 64 + mt * 16 + gid) * ROWB + kcol;
                uint32_t ah[4], al[4];
                ah[0] = *(const uint32_t*)(pa + AH_OFF);
                ah[1] = *(const uint32_t*)(pa + AH_OFF + 8 * ROWB);
                ah[2] = *(const uint32_t*)(pa + AH_OFF + 16);
                ah[3] = *(const uint32_t*)(pa + AH_OFF + 8 * ROWB + 16);
                al[0] = *(const uint32_t*)(pa + AL_OFF);
                al[1] = *(const uint32_t*)(pa + AL_OFF + 8 * ROWB);
                al[2] = *(const uint32_t*)(pa + AL_OFF + 16);
                al[3] = *(const uint32_t*)(pa + AL_OFF + 8 * ROWB + 16);
#pragma unroll
                for (int nt = 0; nt < 4; nt++) {
                    mma_bf16(acc[mt][nt], ah, bh[nt]);
                    mma_bf16(acc[mt][nt], ah, bl[nt]);
                    mma_bf16(acc[mt][nt], al, bh[nt]);
                }
            }
        }
    }

    // epilogue: c0,c1 -> row gid; c2,c3 -> row gid+8; col = 2*ctg within n8
#pragma unroll
    for (int mt = 0; mt < 4; mt++) {
#pragma unroll
        for (int nt = 0; nt < 4; nt++) {
            int r0 = m0 + warp_m * 64 + mt * 16 + gid;
            int col = warp_n * 32 + nt * 8 + 2 * ctg;
            if (r0 < N_NODES)
                *(float2*)(Y + (size_t)r0 * FEAT_CH + col) =
                    make_float2(acc[mt][nt][0], acc[mt][nt][1]);
            int r1 = r0 + 8;
            if (r1 < N_NODES)
                *(float2*)(Y + (size_t)r1 * FEAT_CH + col) =
                    make_float2(acc[mt][nt][2], acc[mt][nt][3]);
        }
    }
}

// ---------------- kernel 3: edge scatter (warp per edge, red.v4) ------------
__global__ __launch_bounds__(256) void edge_kernel(const int* __restrict__ edges) {
    int gt = blockIdx.x * blockDim.x + threadIdx.x;
    int e = gt >> 5;
    int lane = gt & 31;
    if (e >= N_EDGES) return;
    int src = edges[e];
    int dst = edges[N_EDGES + e];
    const float4 v = *(const float4*)(g_yl + (size_t)src * FEAT_CH + lane * 4);
    float* a = g_agg + (size_t)dst * FEAT_CH + lane * 4;
    asm volatile("red.global.add.v4.f32 [%0], {%1, %2, %3, %4};"
                 :: "l"(a), "f"(v.x), "f"(v.y), "f"(v.z), "f"(v.w) : "memory");
    if (lane == 0) atomicAdd(&g_cnt[dst], 1.0f);
}

// ---------------- kernel 4: fused mean+relu+concat+fc1+bn+fc2 ---------------
__global__ __launch_bounds__(256) void final_kernel(
    const float* __restrict__ feats,
    const float* __restrict__ b_sage,
    const float* __restrict__ fc1_w, const float* __restrict__ fc1_b,
    const float* __restrict__ fc2_w, const float* __restrict__ fc2_b,
    const float* __restrict__ bn_g,  const float* __restrict__ bn_b,
    const float* __restrict__ bn_m,  const float* __restrict__ bn_v,
    float* __restrict__ out)
{
    __shared__ __align__(16) float w1s[HIDDEN * FC1_IN];
    __shared__ float vt[256][17];
    __shared__ float invs[256];
    __shared__ float bss[FEAT_CH];
    __shared__ float b1[HIDDEN], sc[HIDDEN], tr[HIDDEN];
    __shared__ float w2s[OUT_CH * HIDDEN], b2[OUT_CH];

    int tid = threadIdx.x;
    int base = blockIdx.x * 256;

    for (int i = tid; i < HIDDEN * FC1_IN; i += 256) w1s[i] = fc1_w[i];
    for (int i = tid; i < FEAT_CH; i += 256) bss[i] = b_sage[i];
    for (int i = tid; i < OUT_CH * HIDDEN; i += 256) w2s[i] = fc2_w[i];
    if (tid < HIDDEN) {
        b1[tid] = fc1_b[tid];
        float s = bn_g[tid] * rsqrtf(bn_v[tid] + 1e-5f);
        sc[tid] = s;
        tr[tid] = bn_b[tid] - bn_m[tid] * s;
    }
    if (tid < OUT_CH) b2[tid] = fc2_b[tid];
    {
        int n = base + tid;
        invs[tid] = (n < N_NODES) ? 1.0f / fmaxf(g_cnt[n], 1.0f) : 0.0f;
    }
    __syncthreads();

    float z[HIDDEN];
#pragma unroll
    for (int j = 0; j < HIDDEN; j++) z[j] = b1[j];

    for (int c = 0; c < 10; c++) {
        // ---- stage ----
        if (c < 8) {
            int i0 = c * 16;
#pragma unroll
            for (int it = 0; it < 4; it++) {
                int idx = tid + it * 256;        // 0..1023
                int n_off = idx >> 2;
                int q = idx & 3;
                int n = base + n_off;
                float4 a = make_float4(0.f, 0.f, 0.f, 0.f);
                float4 y = make_float4(0.f, 0.f, 0.f, 0.f);
                if (n < N_NODES) {
                    a = *(const float4*)(g_agg + (size_t)n * FEAT_CH + i0 + q * 4);
                    y = *(const float4*)(g_yr  + (size_t)n * FEAT_CH + i0 + q * 4);
                }
                float inv = invs[n_off];
                int ib = i0 + q * 4;
                vt[n_off][q * 4 + 0] = fmaxf(fmaf(a.x, inv, bss[ib + 0]) + y.x, 0.f);
                vt[n_off][q * 4 + 1] = fmaxf(fmaf(a.y, inv, bss[ib + 1]) + y.y, 0.f);
                vt[n_off][q * 4 + 2] = fmaxf(fmaf(a.z, inv, bss[ib + 2]) + y.z, 0.f);
                vt[n_off][q * 4 + 3] = fmaxf(fmaf(a.w, inv, bss[ib + 3]) + y.w, 0.f);
            }
        } else if (c == 8) {
#pragma unroll
            for (int it = 0; it < 4; it++) {
                int idx = tid + it * 256;
                int n_off = idx >> 2;
                int q = idx & 3;
                int n = base + n_off;
                float4 e = make_float4(0.f, 0.f, 0.f, 0.f);
                if (n < N_NODES)
                    e = *(const float4*)(feats + (size_t)n * FDIM + IN_SAGE + q * 4);
                vt[n_off][q * 4 + 0] = e.x;
                vt[n_off][q * 4 + 1] = e.y;
                vt[n_off][q * 4 + 2] = e.z;
                vt[n_off][q * 4 + 3] = e.w;
            }
        } else {
            int n = base + tid;
            float4 e = make_float4(0.f, 0.f, 0.f, 0.f);
            if (n < N_NODES)
                e = *(const float4*)(feats + (size_t)n * FDIM + IN_SAGE + 16);
            vt[tid][0] = e.x; vt[tid][1] = e.y; vt[tid][2] = e.z; vt[tid][3] = e.w;
        }
        __syncthreads();

        // ---- compute ----
        int i0 = (c < 9) ? c * 16 : 144;
        int ngrp = (c < 9) ? 4 : 1;
        for (int g = 0; g < ngrp; g++) {
            float v0 = vt[tid][g * 4 + 0];
            float v1 = vt[tid][g * 4 + 1];
            float v2 = vt[tid][g * 4 + 2];
            float v3 = vt[tid][g * 4 + 3];
            const float4* wp = (const float4*)(w1s + i0 + g * 4);
#pragma unroll
            for (int j = 0; j < HIDDEN; j++) {
                float4 w = wp[j * 37];   // 37 float4 = 148 floats = row stride
                z[j] = fmaf(w.x, v0, z[j]);
                z[j] = fmaf(w.y, v1, z[j]);
                z[j] = fmaf(w.z, v2, z[j]);
                z[j] = fmaf(w.w, v3, z[j]);
            }
        }
        __syncthreads();
    }

    int node = base + tid;
    if (node < N_NODES) {
        float h[HIDDEN];
#pragma unroll
        for (int j = 0; j < HIDDEN; j++)
            h[j] = fmaxf(z[j], 0.0f) * sc[j] + tr[j];
#pragma unroll
        for (int k = 0; k < OUT_CH; k++) {
            float s = b2[k];
#pragma unroll
            for (int j = 0; j < HIDDEN; j++)
                s = fmaf(w2s[k * HIDDEN + j], h[j], s);
            out[(size_t)node * OUT_CH + k] = s;
        }
    }
}

// ---------------- launch ----------------------------------------------------
extern "C" void kernel_launch(void* const* d_in, const int* in_sizes, int n_in,
                              void* d_out, int out_size) {
    const float* features = (const float*)d_in[0];
    const int*   edges    = (const int*)  d_in[1];
    // d_in[2] = edges2 (unused), d_in[3] = edge_features (unused)
    const float* w_sage_l = (const float*)d_in[4];
    const float* b_sage_l = (const float*)d_in[5];
    const float* w_sage_r = (const float*)d_in[6];
    const float* fc1_w    = (const float*)d_in[7];
    const float* fc1_b    = (const float*)d_in[8];
    const float* fc2_w    = (const float*)d_in[9];
    const float* fc2_b    = (const float*)d_in[10];
    const float* bn_g     = (const float*)d_in[11];
    const float* bn_b     = (const float*)d_in[12];
    const float* bn_m     = (const float*)d_in[13];
    const float* bn_v     = (const float*)d_in[14];
    float* out = (float*)d_out;

    cudaFuncSetAttribute(gemm_kernel,
                         cudaFuncAttributeMaxDynamicSharedMemorySize, GEMM_SMEM);

    const size_t NA = (size_t)N_NODES * FEAT_CH;
    zero_kernel<<<(int)((NA + 255) / 256), 256>>>();

    prep_w_kernel<<<(2 * FEAT_CH * IN_SAGE) / 256, 256>>>(w_sage_l, w_sage_r);

    gemm_kernel<<<dim3((N_NODES + 127) / 128, 2), 256, GEMM_SMEM>>>(features);

    edge_kernel<<<(N_EDGES * 32) / 256, 256>>>(edges);

    final_kernel<<<(N_NODES + 255) / 256, 256>>>(
        features, b_sage_l, fc1_w, fc1_b, fc2_w, fc2_b,
        bn_g, bn_b, bn_m, bn_v, out);
}

// round 5
// speedup vs baseline: 3.2822x; 1.8200x over previous
#include <cuda_runtime.h>
#include <cuda_bf16.h>
#include <cstdint>

#define N_NODES 70000
#define N_EDGES 800000
#define IN_SAGE 1024
#define FEAT_CH 128
#define EXTRA 20
#define HIDDEN 37        // (128+20)/4
#define OUT_CH 3
#define FDIM 1044
#define FC1_IN 148       // FEAT_CH + EXTRA

// ---------------- scratch (device globals; no allocation allowed) ----------
__device__ float g_yl[(size_t)N_NODES * FEAT_CH];   // x_in @ Wl^T
__device__ float g_yr[(size_t)N_NODES * FEAT_CH];   // x_in @ Wr^T
__device__ float g_agg[(size_t)N_NODES * FEAT_CH];  // segment_sum(y_l[src], dst)
__device__ float g_cnt[N_NODES];
__device__ __align__(16) float g_wt[256 * IN_SAGE]; // [Wl;Wr] tf32-rounded

// ---------------- small helpers --------------------------------------------
__device__ __forceinline__ uint32_t smem_u32(const void* p) {
    uint32_t a;
    asm("{ .reg .u64 t; cvta.to.shared.u64 t, %1; cvt.u32.u64 %0, t; }"
        : "=r"(a) : "l"(p));
    return a;
}

__device__ __forceinline__ uint32_t f2tf32(float v) {
    uint32_t t;
    asm("cvt.rna.tf32.f32 %0, %1;" : "=r"(t) : "f"(v));
    return t;
}

// mma m16n8k8 tf32 (base PTX sm_80+, no 'a' feature)
__device__ __forceinline__ void mma_tf32(float* c, const uint32_t* a, const uint32_t* b) {
    asm volatile(
        "mma.sync.aligned.m16n8k8.row.col.f32.tf32.tf32.f32 "
        "{%0,%1,%2,%3},{%4,%5,%6,%7},{%8,%9},{%0,%1,%2,%3};"
        : "+f"(c[0]), "+f"(c[1]), "+f"(c[2]), "+f"(c[3])
        : "r"(a[0]), "r"(a[1]), "r"(a[2]), "r"(a[3]), "r"(b[0]), "r"(b[1]));
}

// ---------------- kernel 1: zero scratch -----------------------------------
__global__ void zero_kernel() {
    int i = blockIdx.x * blockDim.x + threadIdx.x;
    const int NA4 = N_NODES * FEAT_CH / 4;
    if (i < NA4) ((float4*)g_agg)[i] = make_float4(0.f, 0.f, 0.f, 0.f);
    if (i < N_NODES) g_cnt[i] = 0.0f;
}

// ---------------- kernel 1b: round weights to tf32 --------------------------
__global__ void prep_w_kernel(const float* __restrict__ wl, const float* __restrict__ wr) {
    int i = blockIdx.x * blockDim.x + threadIdx.x;
    if (i >= 256 * IN_SAGE) return;
    int n = i >> 10, k = i & 1023;
    float v = (n < 128) ? wl[n * IN_SAGE + k] : wr[(n - 128) * IN_SAGE + k];
    g_wt[i] = __uint_as_float(f2tf32(v));
}

// ---------------- kernel 2: TF32 fused dual GEMM ----------------------------
// [g_yl | g_yr][m] = X[m, :1024] @ [Wl;Wr]^T.  BM=128, BN=256, BK=32.
// 256 threads = 8 warps, each warp 64x64 tile. 3-stage cp.async pipeline.
#define GBM 128
#define GBK 32
#define NCH (IN_SAGE / GBK)        // 32
#define ASTRIDE 144                // bytes per smem row (36 words) - conflict-free
#define AW 36                      // words per row
#define B_OFF_B (128 * ASTRIDE)    // 18432 bytes
#define B_OFF_W (B_OFF_B / 4)      // 4608 words
#define STAGE_B (B_OFF_B + 256 * ASTRIDE)   // 55296 bytes
#define STAGE_W (STAGE_B / 4)               // 13824 words
#define GEMM_SMEM (3 * STAGE_B)             // 165888

__device__ __forceinline__ void issue_stage(
    uint32_t sbase, const float* __restrict__ X, int m0, int k0, int tid)
{
    // A: 128 rows x 32 floats = 1024 x 16B chunks / 256 thr = 4 each
#pragma unroll
    for (int it = 0; it < 4; it++) {
        int idx = tid + it * 256;
        int row = idx >> 3, q = idx & 7;
        int m = m0 + row;
        int valid = (m < N_NODES);
        const float* src = X + (size_t)(valid ? m : 0) * FDIM + k0 + q * 4;
        asm volatile("cp.async.cg.shared.global [%0], [%1], 16, %2;"
                     :: "r"(sbase + row * ASTRIDE + q * 16), "l"(src),
                        "r"(valid ? 16 : 0));
    }
    // B: 256 rows x 32 floats = 2048 x 16B chunks / 256 thr = 8 each
#pragma unroll
    for (int it = 0; it < 8; it++) {
        int idx = tid + it * 256;
        int row = idx >> 3, q = idx & 7;
        const float* src = g_wt + (size_t)row * IN_SAGE + k0 + q * 4;
        asm volatile("cp.async.cg.shared.global [%0], [%1], 16;"
                     :: "r"(sbase + B_OFF_B + row * ASTRIDE + q * 16), "l"(src));
    }
}

__global__ void __launch_bounds__(256, 1) gemm_kernel(const float* __restrict__ X) {
    extern __shared__ __align__(16) float smf[];
    const uint32_t smb = smem_u32(smf);
    const int tid = threadIdx.x;
    const int wid = tid >> 5;
    const int lane = tid & 31;
    const int gid = lane >> 2;       // 0..7
    const int ctg = lane & 3;        // 0..3
    const int warp_m = wid >> 2;     // 0..1  (M64)
    const int warp_n = wid & 3;      // 0..3  (N64)
    const int m0 = blockIdx.x * GBM;

    float acc[4][8][4];
#pragma unroll
    for (int i = 0; i < 4; i++)
#pragma unroll
        for (int j = 0; j < 8; j++)
#pragma unroll
            for (int r = 0; r < 4; r++) acc[i][j][r] = 0.0f;

    issue_stage(smb, X, m0, 0, tid);
    asm volatile("cp.async.commit_group;" ::: "memory");
    issue_stage(smb + STAGE_B, X, m0, GBK, tid);
    asm volatile("cp.async.commit_group;" ::: "memory");

    for (int c = 0; c < NCH; c++) {
        asm volatile("cp.async.wait_group 1;" ::: "memory");
        __syncthreads();
        if (c + 2 < NCH)
            issue_stage(smb + ((c + 2) % 3) * STAGE_B, X, m0, (c + 2) * GBK, tid);
        asm volatile("cp.async.commit_group;" ::: "memory");

        const float* st = smf + (c % 3) * STAGE_W;
#pragma unroll
        for (int ks = 0; ks < 4; ks++) {
            const int kw = ks * 8 + ctg;
            uint32_t b[8][2];
#pragma unroll
            for (int nt = 0; nt < 8; nt++) {
                const float* pb = st + B_OFF_W + (warp_n * 64 + nt * 8 + gid) * AW + kw;
                b[nt][0] = __float_as_uint(pb[0]);
                b[nt][1] = __float_as_uint(pb[4]);
            }
#pragma unroll
            for (int mt = 0; mt < 4; mt++) {
                const float* pa = st + (warp_m * 64 + mt * 16 + gid) * AW + kw;
                uint32_t a[4];
                a[0] = f2tf32(pa[0]);
                a[1] = f2tf32(pa[8 * AW]);
                a[2] = f2tf32(pa[4]);
                a[3] = f2tf32(pa[8 * AW + 4]);
#pragma unroll
                for (int nt = 0; nt < 8; nt++)
                    mma_tf32(acc[mt][nt], a, b[nt]);
            }
        }
    }

    // epilogue: warp covers rows m0+warp_m*64..+63, cols warp_n*64..+63 of N=256
#pragma unroll
    for (int mt = 0; mt < 4; mt++) {
#pragma unroll
        for (int nt = 0; nt < 8; nt++) {
            int col = warp_n * 64 + nt * 8 + 2 * ctg;       // 0..255
            float* Y = (col < 128) ? g_yl : g_yr;
            int cy = col & 127;
            int r0 = m0 + warp_m * 64 + mt * 16 + gid;
            if (r0 < N_NODES)
                *(float2*)(Y + (size_t)r0 * FEAT_CH + cy) =
                    make_float2(acc[mt][nt][0], acc[mt][nt][1]);
            int r1 = r0 + 8;
            if (r1 < N_NODES)
                *(float2*)(Y + (size_t)r1 * FEAT_CH + cy) =
                    make_float2(acc[mt][nt][2], acc[mt][nt][3]);
        }
    }
}

// ---------------- kernel 3: edge scatter (warp per edge, red.v4) ------------
__global__ __launch_bounds__(256) void edge_kernel(const int* __restrict__ edges) {
    int gt = blockIdx.x * blockDim.x + threadIdx.x;
    int e = gt >> 5;
    int lane = gt & 31;
    if (e >= N_EDGES) return;
    int src = edges[e];
    int dst = edges[N_EDGES + e];
    const float4 v = *(const float4*)(g_yl + (size_t)src * FEAT_CH + lane * 4);
    float* a = g_agg + (size_t)dst * FEAT_CH + lane * 4;
    asm volatile("red.global.add.v4.f32 [%0], {%1, %2, %3, %4};"
                 :: "l"(a), "f"(v.x), "f"(v.y), "f"(v.z), "f"(v.w) : "memory");
    if (lane == 0) atomicAdd(&g_cnt[dst], 1.0f);
}

// ---------------- kernel 4: fused mean+relu+concat+fc1+bn+fc2 ---------------
__global__ __launch_bounds__(256) void final_kernel(
    const float* __restrict__ feats,
    const float* __restrict__ b_sage,
    const float* __restrict__ fc1_w, const float* __restrict__ fc1_b,
    const float* __restrict__ fc2_w, const float* __restrict__ fc2_b,
    const float* __restrict__ bn_g,  const float* __restrict__ bn_b,
    const float* __restrict__ bn_m,  const float* __restrict__ bn_v,
    float* __restrict__ out)
{
    __shared__ __align__(16) float w1s[HIDDEN * FC1_IN];
    __shared__ float vt[256][17];
    __shared__ float invs[256];
    __shared__ float bss[FEAT_CH];
    __shared__ float b1[HIDDEN], sc[HIDDEN], tr[HIDDEN];
    __shared__ float w2s[OUT_CH * HIDDEN], b2[OUT_CH];

    int tid = threadIdx.x;
    int base = blockIdx.x * 256;

    for (int i = tid; i < HIDDEN * FC1_IN; i += 256) w1s[i] = fc1_w[i];
    for (int i = tid; i < FEAT_CH; i += 256) bss[i] = b_sage[i];
    for (int i = tid; i < OUT_CH * HIDDEN; i += 256) w2s[i] = fc2_w[i];
    if (tid < HIDDEN) {
        b1[tid] = fc1_b[tid];
        float s = bn_g[tid] * rsqrtf(bn_v[tid] + 1e-5f);
        sc[tid] = s;
        tr[tid] = bn_b[tid] - bn_m[tid] * s;
    }
    if (tid < OUT_CH) b2[tid] = fc2_b[tid];
    {
        int n = base + tid;
        invs[tid] = (n < N_NODES) ? 1.0f / fmaxf(g_cnt[n], 1.0f) : 0.0f;
    }
    __syncthreads();

    float z[HIDDEN];
#pragma unroll
    for (int j = 0; j < HIDDEN; j++) z[j] = b1[j];

    for (int c = 0; c < 10; c++) {
        if (c < 8) {
            int i0 = c * 16;
#pragma unroll
            for (int it = 0; it < 4; it++) {
                int idx = tid + it * 256;
                int n_off = idx >> 2;
                int q = idx & 3;
                int n = base + n_off;
                float4 a = make_float4(0.f, 0.f, 0.f, 0.f);
                float4 y = make_float4(0.f, 0.f, 0.f, 0.f);
                if (n < N_NODES) {
                    a = *(const float4*)(g_agg + (size_t)n * FEAT_CH + i0 + q * 4);
                    y = *(const float4*)(g_yr  + (size_t)n * FEAT_CH + i0 + q * 4);
                }
                float inv = invs[n_off];
                int ib = i0 + q * 4;
                vt[n_off][q * 4 + 0] = fmaxf(fmaf(a.x, inv, bss[ib + 0]) + y.x, 0.f);
                vt[n_off][q * 4 + 1] = fmaxf(fmaf(a.y, inv, bss[ib + 1]) + y.y, 0.f);
                vt[n_off][q * 4 + 2] = fmaxf(fmaf(a.z, inv, bss[ib + 2]) + y.z, 0.f);
                vt[n_off][q * 4 + 3] = fmaxf(fmaf(a.w, inv, bss[ib + 3]) + y.w, 0.f);
            }
        } else if (c == 8) {
#pragma unroll
            for (int it = 0; it < 4; it++) {
                int idx = tid + it * 256;
                int n_off = idx >> 2;
                int q = idx & 3;
                int n = base + n_off;
                float4 e = make_float4(0.f, 0.f, 0.f, 0.f);
                if (n < N_NODES)
                    e = *(const float4*)(feats + (size_t)n * FDIM + IN_SAGE + q * 4);
                vt[n_off][q * 4 + 0] = e.x;
                vt[n_off][q * 4 + 1] = e.y;
                vt[n_off][q * 4 + 2] = e.z;
                vt[n_off][q * 4 + 3] = e.w;
            }
        } else {
            int n = base + tid;
            float4 e = make_float4(0.f, 0.f, 0.f, 0.f);
            if (n < N_NODES)
                e = *(const float4*)(feats + (size_t)n * FDIM + IN_SAGE + 16);
            vt[tid][0] = e.x; vt[tid][1] = e.y; vt[tid][2] = e.z; vt[tid][3] = e.w;
        }
        __syncthreads();

        int i0 = (c < 9) ? c * 16 : 144;
        int ngrp = (c < 9) ? 4 : 1;
        for (int g = 0; g < ngrp; g++) {
            float v0 = vt[tid][g * 4 + 0];
            float v1 = vt[tid][g * 4 + 1];
            float v2 = vt[tid][g * 4 + 2];
            float v3 = vt[tid][g * 4 + 3];
            const float4* wp = (const float4*)(w1s + i0 + g * 4);
#pragma unroll
            for (int j = 0; j < HIDDEN; j++) {
                float4 w = wp[j * 37];
                z[j] = fmaf(w.x, v0, z[j]);
                z[j] = fmaf(w.y, v1, z[j]);
                z[j] = fmaf(w.z, v2, z[j]);
                z[j] = fmaf(w.w, v3, z[j]);
            }
        }
        __syncthreads();
    }

    int node = base + tid;
    if (node < N_NODES) {
        float h[HIDDEN];
#pragma unroll
        for (int j = 0; j < HIDDEN; j++)
            h[j] = fmaxf(z[j], 0.0f) * sc[j] + tr[j];
#pragma unroll
        for (int k = 0; k < OUT_CH; k++) {
            float s = b2[k];
#pragma unroll
            for (int j = 0; j < HIDDEN; j++)
                s = fmaf(w2s[k * HIDDEN + j], h[j], s);
            out[(size_t)node * OUT_CH + k] = s;
        }
    }
}

// ---------------- launch ----------------------------------------------------
extern "C" void kernel_launch(void* const* d_in, const int* in_sizes, int n_in,
                              void* d_out, int out_size) {
    const float* features = (const float*)d_in[0];
    const int*   edges    = (const int*)  d_in[1];
    // d_in[2] = edges2 (unused), d_in[3] = edge_features (unused)
    const float* w_sage_l = (const float*)d_in[4];
    const float* b_sage_l = (const float*)d_in[5];
    const float* w_sage_r = (const float*)d_in[6];
    const float* fc1_w    = (const float*)d_in[7];
    const float* fc1_b    = (const float*)d_in[8];
    const float* fc2_w    = (const float*)d_in[9];
    const float* fc2_b    = (const float*)d_in[10];
    const float* bn_g     = (const float*)d_in[11];
    const float* bn_b     = (const float*)d_in[12];
    const float* bn_m     = (const float*)d_in[13];
    const float* bn_v     = (const float*)d_in[14];
    float* out = (float*)d_out;

    cudaFuncSetAttribute(gemm_kernel,
                         cudaFuncAttributeMaxDynamicSharedMemorySize, GEMM_SMEM);

    zero_kernel<<<(N_NODES * FEAT_CH / 4 + 255) / 256, 256>>>();

    prep_w_kernel<<<(256 * IN_SAGE) / 256, 256>>>(w_sage_l, w_sage_r);

    gemm_kernel<<<(N_NODES + GBM - 1) / GBM, 256, GEMM_SMEM>>>(features);

    edge_kernel<<<(N_EDGES * 32) / 256, 256>>>(edges);

    final_kernel<<<(N_NODES + 255) / 256, 256>>>(
        features, b_sage_l, fc1_w, fc1_b, fc2_w, fc2_b,
        bn_g, bn_b, bn_m, bn_v, out);
}